// round 14
// baseline (speedup 1.0000x reference)
#include <cuda_runtime.h>
#include <cstdint>

// RegressionLoss: masked SmoothL1 (beta=0.5) sum over N=16,777,216 elements.
//   d = outs - labels; ad = |d|
//   sl1 = ad < 0.5 ? d*d : ad - 0.25       (beta=0.5: 0.5*d*d/0.5 = d*d)
//   keep if ad >= 1/len
//   out[0] = sum(keep ? sl1 : 0)
//
// lens is int32 on device (JAX x64 off). Read as int4.
//
// Kernel function is BYTE-IDENTICAL to the proven R7/R12 binary
// (32.29us, DRAM=80.4%, regs=30). R9/R10 showed any source change to the
// kernel perturbs codegen and regresses. This round changes ONLY the
// launcher: (1) memset node instead of zero kernel (saves ~1-2us launch
// overhead), (2) grid 2368 -> 1184 = one full wave at occ 8 (removes one
// wave transition ~1.3us). [R13 was an infra failure; clean retry.]

__device__ __forceinline__ float sl1_masked(float o, float l, float lenf) {
    float d  = o - l;
    float ad = fabsf(d);
    float v  = (ad < 0.5f) ? (d * d) : (ad - 0.25f);
    // mask: ad >= 1/len  <=>  ad*len >= 1 (len in [1,1000]; edge noise ~1ulp)
    return (ad * lenf >= 1.0f) ? v : 0.0f;
}

__global__ __launch_bounds__(256, 8)
void smoothl1_masked_sum_kernel(const float4* __restrict__ outs4,
                                const float4* __restrict__ labels4,
                                const int4*   __restrict__ lens4,
                                const float*  __restrict__ outs,
                                const float*  __restrict__ labels,
                                const int*    __restrict__ lens,
                                float* __restrict__ out,
                                int nvec, int n) {
    float acc = 0.0f;
    const int stride = gridDim.x * blockDim.x;
    int i = blockIdx.x * blockDim.x + threadIdx.x;

    for (; i < nvec; i += stride) {
        float4 o = outs4[i];
        float4 l = labels4[i];
        int4   L = lens4[i];
        acc += sl1_masked(o.x, l.x, (float)L.x);
        acc += sl1_masked(o.y, l.y, (float)L.y);
        acc += sl1_masked(o.z, l.z, (float)L.z);
        acc += sl1_masked(o.w, l.w, (float)L.w);
    }

    // scalar tail (n not divisible by 4)
    int t = nvec * 4 + blockIdx.x * blockDim.x + threadIdx.x;
    if (t < n) {
        acc += sl1_masked(outs[t], labels[t], (float)lens[t]);
    }

    // warp reduce
    #pragma unroll
    for (int off = 16; off > 0; off >>= 1)
        acc += __shfl_xor_sync(0xffffffffu, acc, off);

    __shared__ float warp_sums[8];
    int lane = threadIdx.x & 31;
    int wid  = threadIdx.x >> 5;
    if (lane == 0) warp_sums[wid] = acc;
    __syncthreads();

    if (wid == 0) {
        float v = (lane < 8) ? warp_sums[lane] : 0.0f;
        #pragma unroll
        for (int off = 4; off > 0; off >>= 1)
            v += __shfl_xor_sync(0xffffffffu, v, off);
        if (lane == 0) atomicAdd(out, v);
    }
}

extern "C" void kernel_launch(void* const* d_in, const int* in_sizes, int n_in,
                              void* d_out, int out_size) {
    const float* outs   = (const float*)d_in[0];
    const float* labels = (const float*)d_in[1];
    const int*   lens   = (const int*)d_in[2];   // int32 on device (JAX x64 off)
    float* out = (float*)d_out;
    const int n    = in_sizes[0];
    const int nvec = n >> 2;

    // graph-capturable memset node (cheaper than a kernel launch)
    cudaMemsetAsync(out, 0, sizeof(float));

    const int threads = 256;
    int blocks = 148 * 8;    // exactly one wave at occ 8 (no wave transition)
    int max_blocks = (nvec + threads - 1) / threads;
    if (blocks > max_blocks && max_blocks > 0) blocks = max_blocks;
    if (blocks < 1) blocks = 1;

    smoothl1_masked_sum_kernel<<<blocks, threads>>>(
        (const float4*)outs, (const float4*)labels, (const int4*)lens,
        outs, labels, lens, out, nvec, n);
}

// round 15
// speedup vs baseline: 1.0074x; 1.0074x over previous
#include <cuda_runtime.h>
#include <cstdint>

// RegressionLoss: masked SmoothL1 (beta=0.5) sum over N=16,777,216 elements.
//   d = outs - labels; ad = |d|
//   sl1 = ad < 0.5 ? d*d : ad - 0.25       (beta=0.5: 0.5*d*d/0.5 = d*d)
//   keep if ad >= 1/len
//   out[0] = sum(keep ? sl1 : 0)
//
// lens is int32 on device (JAX x64 off). Read as int4.
//
// Kernel is BYTE-IDENTICAL to the proven R7/R12 binary (32.29us, DRAM=80.4%,
// regs=30). Grid sweep: 888->35.6us, 1184->33.5us, 2368->32.29us — multi-wave
// self-balancing wins; grid stays 2368. Memset node measured cheaper than the
// zero kernel (overhead 1.41us vs 2.30us). This round = 2368 + memset.

__device__ __forceinline__ float sl1_masked(float o, float l, float lenf) {
    float d  = o - l;
    float ad = fabsf(d);
    float v  = (ad < 0.5f) ? (d * d) : (ad - 0.25f);
    // mask: ad >= 1/len  <=>  ad*len >= 1 (len in [1,1000]; edge noise ~1ulp)
    return (ad * lenf >= 1.0f) ? v : 0.0f;
}

__global__ __launch_bounds__(256, 8)
void smoothl1_masked_sum_kernel(const float4* __restrict__ outs4,
                                const float4* __restrict__ labels4,
                                const int4*   __restrict__ lens4,
                                const float*  __restrict__ outs,
                                const float*  __restrict__ labels,
                                const int*    __restrict__ lens,
                                float* __restrict__ out,
                                int nvec, int n) {
    float acc = 0.0f;
    const int stride = gridDim.x * blockDim.x;
    int i = blockIdx.x * blockDim.x + threadIdx.x;

    for (; i < nvec; i += stride) {
        float4 o = outs4[i];
        float4 l = labels4[i];
        int4   L = lens4[i];
        acc += sl1_masked(o.x, l.x, (float)L.x);
        acc += sl1_masked(o.y, l.y, (float)L.y);
        acc += sl1_masked(o.z, l.z, (float)L.z);
        acc += sl1_masked(o.w, l.w, (float)L.w);
    }

    // scalar tail (n not divisible by 4)
    int t = nvec * 4 + blockIdx.x * blockDim.x + threadIdx.x;
    if (t < n) {
        acc += sl1_masked(outs[t], labels[t], (float)lens[t]);
    }

    // warp reduce
    #pragma unroll
    for (int off = 16; off > 0; off >>= 1)
        acc += __shfl_xor_sync(0xffffffffu, acc, off);

    __shared__ float warp_sums[8];
    int lane = threadIdx.x & 31;
    int wid  = threadIdx.x >> 5;
    if (lane == 0) warp_sums[wid] = acc;
    __syncthreads();

    if (wid == 0) {
        float v = (lane < 8) ? warp_sums[lane] : 0.0f;
        #pragma unroll
        for (int off = 4; off > 0; off >>= 1)
            v += __shfl_xor_sync(0xffffffffu, v, off);
        if (lane == 0) atomicAdd(out, v);
    }
}

extern "C" void kernel_launch(void* const* d_in, const int* in_sizes, int n_in,
                              void* d_out, int out_size) {
    const float* outs   = (const float*)d_in[0];
    const float* labels = (const float*)d_in[1];
    const int*   lens   = (const int*)d_in[2];   // int32 on device (JAX x64 off)
    float* out = (float*)d_out;
    const int n    = in_sizes[0];
    const int nvec = n >> 2;

    // graph-capturable memset node (cheaper than a kernel launch)
    cudaMemsetAsync(out, 0, sizeof(float));

    const int threads = 256;
    int blocks = 148 * 16;   // 2368 — best measured (multi-wave balancing)
    int max_blocks = (nvec + threads - 1) / threads;
    if (blocks > max_blocks && max_blocks > 0) blocks = max_blocks;
    if (blocks < 1) blocks = 1;

    smoothl1_masked_sum_kernel<<<blocks, threads>>>(
        (const float4*)outs, (const float4*)labels, (const int4*)lens,
        outs, labels, lens, out, nvec, n);
}